// round 2
// baseline (speedup 1.0000x reference)
#include <cuda_runtime.h>
#include <math.h>

// Problem constants (fixed by the reference)
#define Bsz   4096
#define INDIM 1024
#define Dm    512
#define Nn    8
#define Ss    128
#define HOPS  4
#define MAXT  72      // max token tiles per hop: 4096/64 + 8

// -------- device scratch (no allocations allowed) --------
__device__ float g_z[Bsz * Dm];        // z / ping buffer
__device__ float g_buf[Bsz * Dm];      // pong buffer
__device__ float g_symmean[Bsz * Ss];
__device__ int   g_prog[Bsz * HOPS];
__device__ int   g_order[HOPS][Bsz];
__device__ int   g_tileE[HOPS][MAXT];
__device__ int   g_tileS[HOPS][MAXT];
__device__ int   g_tileC[HOPS][MAXT];
__device__ int   g_numTiles[HOPS];

__device__ __forceinline__ float gelu_tanh(float x) {
    // JAX default gelu (approximate=True)
    float x3 = x * x * x;
    return 0.5f * x * (1.0f + tanhf(0.7978845608028654f * (x + 0.044715f * x3)));
}

#define MMA16()                                                                              \
    _Pragma("unroll")                                                                        \
    for (int kk = 0; kk < 16; kk++) {                                                        \
        float4 a = *reinterpret_cast<const float4*>(&As[kk][ty]);                            \
        float4 b = *reinterpret_cast<const float4*>(&Bs[kk][tx]);                            \
        acc[0][0] = fmaf(a.x, b.x, acc[0][0]); acc[0][1] = fmaf(a.x, b.y, acc[0][1]);        \
        acc[0][2] = fmaf(a.x, b.z, acc[0][2]); acc[0][3] = fmaf(a.x, b.w, acc[0][3]);        \
        acc[1][0] = fmaf(a.y, b.x, acc[1][0]); acc[1][1] = fmaf(a.y, b.y, acc[1][1]);        \
        acc[1][2] = fmaf(a.y, b.z, acc[1][2]); acc[1][3] = fmaf(a.y, b.w, acc[1][3]);        \
        acc[2][0] = fmaf(a.z, b.x, acc[2][0]); acc[2][1] = fmaf(a.z, b.y, acc[2][1]);        \
        acc[2][2] = fmaf(a.z, b.z, acc[2][2]); acc[2][3] = fmaf(a.z, b.w, acc[2][3]);        \
        acc[3][0] = fmaf(a.w, b.x, acc[3][0]); acc[3][1] = fmaf(a.w, b.y, acc[3][1]);        \
        acc[3][2] = fmaf(a.w, b.z, acc[3][2]); acc[3][3] = fmaf(a.w, b.w, acc[3][3]);        \
    }

// ================= GEMM 1: z = x @ W_in + b_in   [4096,1024]x[1024,512] ==============
__global__ __launch_bounds__(256) void gemm_z_kernel(
    const float* __restrict__ A, const float* __restrict__ W, const float* __restrict__ bias) {
    __shared__ __align__(16) float As[16][68];
    __shared__ __align__(16) float Bs[16][64];
    const int bm = blockIdx.x * 64, bn = blockIdx.y * 64;
    const int tid  = threadIdx.x;
    const int arow = tid >> 2,  akq = (tid & 3) * 4;
    const int brow = tid >> 4,  bnq = (tid & 15) * 4;
    const int ty   = (tid >> 4) * 4, tx = (tid & 15) * 4;
    float acc[4][4] = {};
    const float* aptr = A + (bm + arow) * INDIM + akq;
    for (int k0 = 0; k0 < INDIM; k0 += 16) {
        float4 av = *reinterpret_cast<const float4*>(aptr + k0);
        float4 bv = *reinterpret_cast<const float4*>(W + (k0 + brow) * Dm + bn + bnq);
        As[akq + 0][arow] = av.x; As[akq + 1][arow] = av.y;
        As[akq + 2][arow] = av.z; As[akq + 3][arow] = av.w;
        *reinterpret_cast<float4*>(&Bs[brow][bnq]) = bv;
        __syncthreads();
        MMA16();
        __syncthreads();
    }
#pragma unroll
    for (int i = 0; i < 4; i++)
#pragma unroll
        for (int j = 0; j < 4; j++)
            g_z[(bm + ty + i) * Dm + bn + tx + j] = acc[i][j] + bias[bn + tx + j];
}

// ========= GEMM 2: sym[b, n*128+s] = sum_d z[b,d] * sym_W[n,d,s]   (K=512) ==========
__global__ __launch_bounds__(256) void gemm_sym_kernel(
    const float* __restrict__ symW, float* __restrict__ symOut) {
    __shared__ __align__(16) float As[16][68];
    __shared__ __align__(16) float Bs[16][64];
    const int bm = blockIdx.x * 64, bn = blockIdx.y * 64;   // bn over 1024 cols
    const int n_id = bn >> 7, s0 = bn & 127;
    const int tid  = threadIdx.x;
    const int arow = tid >> 2,  akq = (tid & 3) * 4;
    const int brow = tid >> 4,  bnq = (tid & 15) * 4;
    const int ty   = (tid >> 4) * 4, tx = (tid & 15) * 4;
    float acc[4][4] = {};
    const float* aptr = g_z + (bm + arow) * Dm + akq;
    const float* bbase = symW + n_id * (Dm * Ss) + s0 + bnq;
    for (int k0 = 0; k0 < Dm; k0 += 16) {
        float4 av = *reinterpret_cast<const float4*>(aptr + k0);
        float4 bv = *reinterpret_cast<const float4*>(bbase + (k0 + brow) * Ss);
        As[akq + 0][arow] = av.x; As[akq + 1][arow] = av.y;
        As[akq + 2][arow] = av.z; As[akq + 3][arow] = av.w;
        *reinterpret_cast<float4*>(&Bs[brow][bnq]) = bv;
        __syncthreads();
        MMA16();
        __syncthreads();
    }
#pragma unroll
    for (int i = 0; i < 4; i++)
#pragma unroll
        for (int j = 0; j < 4; j++)
            symOut[(bm + ty + i) * (Nn * Ss) + bn + tx + j] = acc[i][j];
}

// ================== symmean[b,s] = mean_n sym[b,n,s] ==================
__global__ void mean_kernel(const float* __restrict__ symOut) {
    int i = blockIdx.x * blockDim.x + threadIdx.x;   // < 4096*128
    int b = i >> 7, s = i & 127;
    const float* p = symOut + b * (Nn * Ss) + s;
    float sum = 0.f;
#pragma unroll
    for (int n = 0; n < Nn; n++) sum += p[n * Ss];
    g_symmean[i] = sum * 0.125f;
}

// ====== router: logits (fp64 accumulation for argmax fidelity) + argmax -> prog ======
// 8 independent fp64 accumulators break the serial DFMA chain (ILP=8).
__global__ __launch_bounds__(288) void router_kernel(
    const float* __restrict__ RW, const float* __restrict__ rb, float* __restrict__ progf) {
    __shared__ float rin[8][644];
    __shared__ float lg[8][36];
    const int b0 = blockIdx.x * 8;
    const int tid = threadIdx.x;
    for (int i = tid; i < 8 * 640; i += 288) {
        int t = i / 640, k = i - t * 640;
        rin[t][k] = (k < Dm) ? g_z[(b0 + t) * Dm + k]
                             : g_symmean[(b0 + t) * Ss + (k - Dm)];
    }
    __syncthreads();
    {
        const int t = tid / 36, j = tid - t * 36;
        const float* rw = RW + j;
        double a0 = 0.0, a1 = 0.0, a2 = 0.0, a3 = 0.0;
        double a4 = 0.0, a5 = 0.0, a6 = 0.0, a7 = 0.0;
#pragma unroll 4
        for (int k = 0; k < 640; k += 8) {
            a0 += (double)rin[t][k + 0] * (double)rw[(k + 0) * 36];
            a1 += (double)rin[t][k + 1] * (double)rw[(k + 1) * 36];
            a2 += (double)rin[t][k + 2] * (double)rw[(k + 2) * 36];
            a3 += (double)rin[t][k + 3] * (double)rw[(k + 3) * 36];
            a4 += (double)rin[t][k + 4] * (double)rw[(k + 4) * 36];
            a5 += (double)rin[t][k + 5] * (double)rw[(k + 5) * 36];
            a6 += (double)rin[t][k + 6] * (double)rw[(k + 6) * 36];
            a7 += (double)rin[t][k + 7] * (double)rw[(k + 7) * 36];
        }
        double acc = (((a0 + a1) + (a2 + a3)) + ((a4 + a5) + (a6 + a7))) + (double)rb[j];
        lg[t][j] = (float)acc;
    }
    __syncthreads();
    if (tid < 32) {
        int t = tid >> 2, h = tid & 3;
        const float* l = &lg[t][h * 9];
        float best = l[0]; int bi = 0;
#pragma unroll
        for (int j = 1; j < 9; j++)
            if (l[j] > best) { best = l[j]; bi = j; }   // first-max tie-break, like jnp.argmax
        g_prog[(b0 + t) * HOPS + h] = bi;
        progf[(b0 + t) * HOPS + h] = (float)bi;
    }
}

// ======= schedule: group active tokens by (hop, expert); build 64-row tiles =======
__global__ void schedule_kernel() {
    __shared__ int cnt[HOPS][Nn];
    __shared__ int cur[HOPS][Nn];
    const int tid = threadIdx.x;
    if (tid < HOPS * Nn) cnt[tid / Nn][tid % Nn] = 0;
    __syncthreads();
    for (int b = tid; b < Bsz; b += blockDim.x) {
        bool act = true;
        for (int t = 0; t < HOPS; t++) {
            int e = g_prog[b * HOPS + t];
            act = act && (e != Nn);
            if (act) atomicAdd(&cnt[t][e], 1);
        }
    }
    __syncthreads();
    if (tid < HOPS) {
        int t = tid, p = 0, nt = 0;
        for (int e = 0; e < Nn; e++) {
            cur[t][e] = p;
            int c = cnt[t][e], q = p;
            while (c > 0) {
                g_tileE[t][nt] = e; g_tileS[t][nt] = q;
                g_tileC[t][nt] = (c < 64) ? c : 64;
                q += 64; c -= 64; nt++;
            }
            p += cnt[t][e];
        }
        g_numTiles[t] = nt;
    }
    __syncthreads();
    for (int b = tid; b < Bsz; b += blockDim.x) {
        bool act = true;
        for (int t = 0; t < HOPS; t++) {
            int e = g_prog[b * HOPS + t];
            act = act && (e != Nn);
            if (act) { int p = atomicAdd(&cur[t][e], 1); g_order[t][p] = b; }
        }
    }
}

// ===== copy cur -> next (inactive tokens keep their value; GEMM overwrites actives) =====
__global__ void copy_kernel(int srcSel, int dstSel, float* __restrict__ outbase) {
    const float* s = (srcSel == 0) ? g_z : g_buf;
    float* d = (dstSel == 0) ? g_z : (dstSel == 1) ? g_buf : outbase;
    int i = blockIdx.x * blockDim.x + threadIdx.x;   // exactly B*D/4 threads
    reinterpret_cast<float4*>(d)[i] = reinterpret_cast<const float4*>(s)[i];
}

// ===== grouped gather/scatter GEMM: dst[tok] = gelu(src[tok] @ ops_W[e] + ops_b[e]) =====
__global__ __launch_bounds__(256) void hop_kernel(
    int hop, int srcSel, int dstSel, float* __restrict__ outbase,
    const float* __restrict__ opsW, const float* __restrict__ opsB) {
    if ((int)blockIdx.x >= g_numTiles[hop]) return;
    const float* src = (srcSel == 0) ? g_z : g_buf;
    float* dst = (dstSel == 0) ? g_z : (dstSel == 1) ? g_buf : outbase;
    const int e     = g_tileE[hop][blockIdx.x];
    const int start = g_tileS[hop][blockIdx.x];
    const int cnt   = g_tileC[hop][blockIdx.x];
    const int bn    = blockIdx.y * 64;
    __shared__ int toks[64];
    __shared__ __align__(16) float As[16][68];
    __shared__ __align__(16) float Bs[16][64];
    const int tid  = threadIdx.x;
    const int arow = tid >> 2,  akq = (tid & 3) * 4;
    const int brow = tid >> 4,  bnq = (tid & 15) * 4;
    const int ty   = (tid >> 4) * 4, tx = (tid & 15) * 4;
    if (tid < 64) toks[tid] = (tid < cnt) ? g_order[hop][start + tid] : -1;
    __syncthreads();
    const float* W = opsW + e * (Dm * Dm);
    float acc[4][4] = {};
    const int mytok = toks[arow];
    for (int k0 = 0; k0 < Dm; k0 += 16) {
        float4 av = make_float4(0.f, 0.f, 0.f, 0.f);
        if (mytok >= 0)
            av = *reinterpret_cast<const float4*>(src + mytok * Dm + k0 + akq);
        float4 bv = *reinterpret_cast<const float4*>(W + (k0 + brow) * Dm + bn + bnq);
        As[akq + 0][arow] = av.x; As[akq + 1][arow] = av.y;
        As[akq + 2][arow] = av.z; As[akq + 3][arow] = av.w;
        *reinterpret_cast<float4*>(&Bs[brow][bnq]) = bv;
        __syncthreads();
        MMA16();
        __syncthreads();
    }
#pragma unroll
    for (int i = 0; i < 4; i++) {
        int tk = toks[ty + i];
        if (tk < 0) continue;
#pragma unroll
        for (int j = 0; j < 4; j++)
            dst[tk * Dm + bn + tx + j] =
                gelu_tanh(acc[i][j] + opsB[e * Dm + bn + tx + j]);
    }
}

// =========================== launch ===========================
extern "C" void kernel_launch(void* const* d_in, const int* in_sizes, int n_in,
                              void* d_out, int out_size) {
    const float* x        = (const float*)d_in[0];
    const float* W_in     = (const float*)d_in[1];
    const float* b_in     = (const float*)d_in[2];
    const float* ops_W    = (const float*)d_in[3];
    const float* ops_b    = (const float*)d_in[4];
    const float* sym_W    = (const float*)d_in[5];
    const float* router_W = (const float*)d_in[6];
    const float* router_b = (const float*)d_in[7];
    (void)in_sizes; (void)n_in; (void)out_size;

    float* out   = (float*)d_out;                 // [B, D]
    float* progf = out + Bsz * Dm;                // [B, HOPS] as float
    float* sym   = progf + Bsz * HOPS;            // [B, N, S]

    const int copyBlocks = (Bsz * Dm / 4) / 256;  // 2048

    gemm_z_kernel  <<<dim3(Bsz / 64, Dm / 64), 256>>>(x, W_in, b_in);
    gemm_sym_kernel<<<dim3(Bsz / 64, (Nn * Ss) / 64), 256>>>(sym_W, sym);
    mean_kernel    <<<(Bsz * Ss) / 256, 256>>>(sym);
    router_kernel  <<<Bsz / 8, 288>>>(router_W, router_b, progf);
    schedule_kernel<<<1, 512>>>();

    // hop 0: z -> buf
    copy_kernel<<<copyBlocks, 256>>>(0, 1, out);
    hop_kernel <<<dim3(MAXT, Dm / 64), 256>>>(0, 0, 1, out, ops_W, ops_b);
    // hop 1: buf -> z
    copy_kernel<<<copyBlocks, 256>>>(1, 0, out);
    hop_kernel <<<dim3(MAXT, Dm / 64), 256>>>(1, 1, 0, out, ops_W, ops_b);
    // hop 2: z -> buf
    copy_kernel<<<copyBlocks, 256>>>(0, 1, out);
    hop_kernel <<<dim3(MAXT, Dm / 64), 256>>>(2, 0, 1, out, ops_W, ops_b);
    // hop 3: buf -> d_out (final)
    copy_kernel<<<copyBlocks, 256>>>(1, 2, out);
    hop_kernel <<<dim3(MAXT, Dm / 64), 256>>>(3, 1, 2, out, ops_W, ops_b);
}

// round 3
// speedup vs baseline: 1.8529x; 1.8529x over previous
#include <cuda_runtime.h>
#include <math.h>

// Problem constants (fixed by the reference)
#define Bsz   4096
#define INDIM 1024
#define Dm    512
#define Nn    8
#define Ss    128
#define HOPS  4
#define MAXT  72      // max token tiles per hop: 4096/64 + 8

// -------- device scratch (no allocations allowed) --------
__device__ float g_z[Bsz * Dm];        // z / ping buffer
__device__ float g_buf[Bsz * Dm];      // pong buffer
__device__ float g_symmean[Bsz * Ss];
__device__ int   g_prog[Bsz * HOPS];
__device__ int   g_order[HOPS][Bsz];
__device__ int   g_tileE[HOPS][MAXT];
__device__ int   g_tileS[HOPS][MAXT];
__device__ int   g_tileC[HOPS][MAXT];
__device__ int   g_numTiles[HOPS];

__device__ __forceinline__ float gelu_tanh(float x) {
    // JAX default gelu (approximate=True)
    float x3 = x * x * x;
    return 0.5f * x * (1.0f + tanhf(0.7978845608028654f * (x + 0.044715f * x3)));
}

#define MMA16()                                                                              \
    _Pragma("unroll")                                                                        \
    for (int kk = 0; kk < 16; kk++) {                                                        \
        float4 a = *reinterpret_cast<const float4*>(&As[kk][ty]);                            \
        float4 b = *reinterpret_cast<const float4*>(&Bs[kk][tx]);                            \
        acc[0][0] = fmaf(a.x, b.x, acc[0][0]); acc[0][1] = fmaf(a.x, b.y, acc[0][1]);        \
        acc[0][2] = fmaf(a.x, b.z, acc[0][2]); acc[0][3] = fmaf(a.x, b.w, acc[0][3]);        \
        acc[1][0] = fmaf(a.y, b.x, acc[1][0]); acc[1][1] = fmaf(a.y, b.y, acc[1][1]);        \
        acc[1][2] = fmaf(a.y, b.z, acc[1][2]); acc[1][3] = fmaf(a.y, b.w, acc[1][3]);        \
        acc[2][0] = fmaf(a.z, b.x, acc[2][0]); acc[2][1] = fmaf(a.z, b.y, acc[2][1]);        \
        acc[2][2] = fmaf(a.z, b.z, acc[2][2]); acc[2][3] = fmaf(a.z, b.w, acc[2][3]);        \
        acc[3][0] = fmaf(a.w, b.x, acc[3][0]); acc[3][1] = fmaf(a.w, b.y, acc[3][1]);        \
        acc[3][2] = fmaf(a.w, b.z, acc[3][2]); acc[3][3] = fmaf(a.w, b.w, acc[3][3]);        \
    }

// ================= GEMM 1: z = x @ W_in + b_in   [4096,1024]x[1024,512] ==============
__global__ __launch_bounds__(256) void gemm_z_kernel(
    const float* __restrict__ A, const float* __restrict__ W, const float* __restrict__ bias) {
    __shared__ __align__(16) float As[16][68];
    __shared__ __align__(16) float Bs[16][64];
    const int bm = blockIdx.x * 64, bn = blockIdx.y * 64;
    const int tid  = threadIdx.x;
    const int arow = tid >> 2,  akq = (tid & 3) * 4;
    const int brow = tid >> 4,  bnq = (tid & 15) * 4;
    const int ty   = (tid >> 4) * 4, tx = (tid & 15) * 4;
    float acc[4][4] = {};
    const float* aptr = A + (bm + arow) * INDIM + akq;
    for (int k0 = 0; k0 < INDIM; k0 += 16) {
        float4 av = *reinterpret_cast<const float4*>(aptr + k0);
        float4 bv = *reinterpret_cast<const float4*>(W + (k0 + brow) * Dm + bn + bnq);
        As[akq + 0][arow] = av.x; As[akq + 1][arow] = av.y;
        As[akq + 2][arow] = av.z; As[akq + 3][arow] = av.w;
        *reinterpret_cast<float4*>(&Bs[brow][bnq]) = bv;
        __syncthreads();
        MMA16();
        __syncthreads();
    }
#pragma unroll
    for (int i = 0; i < 4; i++)
#pragma unroll
        for (int j = 0; j < 4; j++)
            g_z[(bm + ty + i) * Dm + bn + tx + j] = acc[i][j] + bias[bn + tx + j];
}

// ========= GEMM 2: sym[b, n*128+s] = sum_d z[b,d] * sym_W[n,d,s]   (K=512) ==========
__global__ __launch_bounds__(256) void gemm_sym_kernel(
    const float* __restrict__ symW, float* __restrict__ symOut) {
    __shared__ __align__(16) float As[16][68];
    __shared__ __align__(16) float Bs[16][64];
    const int bm = blockIdx.x * 64, bn = blockIdx.y * 64;   // bn over 1024 cols
    const int n_id = bn >> 7, s0 = bn & 127;
    const int tid  = threadIdx.x;
    const int arow = tid >> 2,  akq = (tid & 3) * 4;
    const int brow = tid >> 4,  bnq = (tid & 15) * 4;
    const int ty   = (tid >> 4) * 4, tx = (tid & 15) * 4;
    float acc[4][4] = {};
    const float* aptr = g_z + (bm + arow) * Dm + akq;
    const float* bbase = symW + n_id * (Dm * Ss) + s0 + bnq;
    for (int k0 = 0; k0 < Dm; k0 += 16) {
        float4 av = *reinterpret_cast<const float4*>(aptr + k0);
        float4 bv = *reinterpret_cast<const float4*>(bbase + (k0 + brow) * Ss);
        As[akq + 0][arow] = av.x; As[akq + 1][arow] = av.y;
        As[akq + 2][arow] = av.z; As[akq + 3][arow] = av.w;
        *reinterpret_cast<float4*>(&Bs[brow][bnq]) = bv;
        __syncthreads();
        MMA16();
        __syncthreads();
    }
#pragma unroll
    for (int i = 0; i < 4; i++)
#pragma unroll
        for (int j = 0; j < 4; j++)
            symOut[(bm + ty + i) * (Nn * Ss) + bn + tx + j] = acc[i][j];
}

// ================== symmean[b,s] = mean_n sym[b,n,s] ==================
__global__ void mean_kernel(const float* __restrict__ symOut) {
    int i = blockIdx.x * blockDim.x + threadIdx.x;   // < 4096*128
    int b = i >> 7, s = i & 127;
    const float* p = symOut + b * (Nn * Ss) + s;
    float sum = 0.f;
#pragma unroll
    for (int n = 0; n < Nn; n++) sum += p[n * Ss];
    g_symmean[i] = sum * 0.125f;
}

// ====== router: compensated-fp32 logits (error-free transforms) + argmax -> prog ======
// fp64 is ~1 TF/s on B300 (DFMA rt ~64 cyc) -> was 610us. TwoProdFMA + Knuth TwoSum
// on the FFMA pipe gives ~1e-11 relative accuracy at fp32 throughput.
// Intrinsics (__fmul_rn etc) prevent fast-math contraction from breaking the EFTs.
__global__ __launch_bounds__(288) void router_kernel(
    const float* __restrict__ RW, const float* __restrict__ rb, float* __restrict__ progf) {
    __shared__ float rin[8][644];
    __shared__ float lg[8][36];
    const int b0 = blockIdx.x * 8;
    const int tid = threadIdx.x;
    for (int i = tid; i < 8 * 640; i += 288) {
        int t = i / 640, k = i - t * 640;
        rin[t][k] = (k < Dm) ? g_z[(b0 + t) * Dm + k]
                             : g_symmean[(b0 + t) * Ss + (k - Dm)];
    }
    __syncthreads();
    {
        const int t = tid / 36, j = tid - t * 36;
        const float* rw = RW + j;
        float s[4] = {0.f, 0.f, 0.f, 0.f};
        float c[4] = {0.f, 0.f, 0.f, 0.f};
#pragma unroll 2
        for (int k = 0; k < 640; k += 4) {
#pragma unroll
            for (int i = 0; i < 4; i++) {
                float x = rin[t][k + i];
                float w = __ldg(&rw[(k + i) * 36]);
                float p = __fmul_rn(x, w);
                float e = __fmaf_rn(x, w, -p);           // exact product error
                // Knuth TwoSum(s[i], p) — unconditional, exact
                float t1  = __fadd_rn(s[i], p);
                float bb  = __fsub_rn(t1, s[i]);
                float er1 = __fadd_rn(__fsub_rn(s[i], __fsub_rn(t1, bb)),
                                      __fsub_rn(p, bb));
                s[i] = t1;
                c[i] = __fadd_rn(c[i], __fadd_rn(er1, e));
            }
        }
        // combine the 4 double-single partials + bias
        float S = rb[j], C = 0.f;
#pragma unroll
        for (int i = 0; i < 4; i++) {
            float t1  = __fadd_rn(S, s[i]);
            float bb  = __fsub_rn(t1, S);
            float er1 = __fadd_rn(__fsub_rn(S, __fsub_rn(t1, bb)),
                                  __fsub_rn(s[i], bb));
            S = t1;
            C = __fadd_rn(C, __fadd_rn(er1, c[i]));
        }
        lg[t][j] = __fadd_rn(S, C);
    }
    __syncthreads();
    if (tid < 32) {
        int t = tid >> 2, h = tid & 3;
        const float* l = &lg[t][h * 9];
        float best = l[0]; int bi = 0;
#pragma unroll
        for (int j = 1; j < 9; j++)
            if (l[j] > best) { best = l[j]; bi = j; }   // first-max tie-break, like jnp.argmax
        g_prog[(b0 + t) * HOPS + h] = bi;
        progf[(b0 + t) * HOPS + h] = (float)bi;
    }
}

// ======= schedule: group active tokens by (hop, expert); build 64-row tiles =======
__global__ void schedule_kernel() {
    __shared__ int cnt[HOPS][Nn];
    __shared__ int cur[HOPS][Nn];
    const int tid = threadIdx.x;
    if (tid < HOPS * Nn) cnt[tid / Nn][tid % Nn] = 0;
    __syncthreads();
    for (int b = tid; b < Bsz; b += blockDim.x) {
        bool act = true;
        for (int t = 0; t < HOPS; t++) {
            int e = g_prog[b * HOPS + t];
            act = act && (e != Nn);
            if (act) atomicAdd(&cnt[t][e], 1);
        }
    }
    __syncthreads();
    if (tid < HOPS) {
        int t = tid, p = 0, nt = 0;
        for (int e = 0; e < Nn; e++) {
            cur[t][e] = p;
            int c = cnt[t][e], q = p;
            while (c > 0) {
                g_tileE[t][nt] = e; g_tileS[t][nt] = q;
                g_tileC[t][nt] = (c < 64) ? c : 64;
                q += 64; c -= 64; nt++;
            }
            p += cnt[t][e];
        }
        g_numTiles[t] = nt;
    }
    __syncthreads();
    for (int b = tid; b < Bsz; b += blockDim.x) {
        bool act = true;
        for (int t = 0; t < HOPS; t++) {
            int e = g_prog[b * HOPS + t];
            act = act && (e != Nn);
            if (act) { int p = atomicAdd(&cur[t][e], 1); g_order[t][p] = b; }
        }
    }
}

// ===== copy cur -> next (inactive tokens keep their value; GEMM overwrites actives) =====
__global__ void copy_kernel(int srcSel, int dstSel, float* __restrict__ outbase) {
    const float* s = (srcSel == 0) ? g_z : g_buf;
    float* d = (dstSel == 0) ? g_z : (dstSel == 1) ? g_buf : outbase;
    int i = blockIdx.x * blockDim.x + threadIdx.x;   // exactly B*D/4 threads
    reinterpret_cast<float4*>(d)[i] = reinterpret_cast<const float4*>(s)[i];
}

// ===== grouped gather/scatter GEMM: dst[tok] = gelu(src[tok] @ ops_W[e] + ops_b[e]) =====
__global__ __launch_bounds__(256) void hop_kernel(
    int hop, int srcSel, int dstSel, float* __restrict__ outbase,
    const float* __restrict__ opsW, const float* __restrict__ opsB) {
    if ((int)blockIdx.x >= g_numTiles[hop]) return;
    const float* src = (srcSel == 0) ? g_z : g_buf;
    float* dst = (dstSel == 0) ? g_z : (dstSel == 1) ? g_buf : outbase;
    const int e     = g_tileE[hop][blockIdx.x];
    const int start = g_tileS[hop][blockIdx.x];
    const int cnt   = g_tileC[hop][blockIdx.x];
    const int bn    = blockIdx.y * 64;
    __shared__ int toks[64];
    __shared__ __align__(16) float As[16][68];
    __shared__ __align__(16) float Bs[16][64];
    const int tid  = threadIdx.x;
    const int arow = tid >> 2,  akq = (tid & 3) * 4;
    const int brow = tid >> 4,  bnq = (tid & 15) * 4;
    const int ty   = (tid >> 4) * 4, tx = (tid & 15) * 4;
    if (tid < 64) toks[tid] = (tid < cnt) ? g_order[hop][start + tid] : -1;
    __syncthreads();
    const float* W = opsW + e * (Dm * Dm);
    float acc[4][4] = {};
    const int mytok = toks[arow];
    for (int k0 = 0; k0 < Dm; k0 += 16) {
        float4 av = make_float4(0.f, 0.f, 0.f, 0.f);
        if (mytok >= 0)
            av = *reinterpret_cast<const float4*>(src + mytok * Dm + k0 + akq);
        float4 bv = *reinterpret_cast<const float4*>(W + (k0 + brow) * Dm + bn + bnq);
        As[akq + 0][arow] = av.x; As[akq + 1][arow] = av.y;
        As[akq + 2][arow] = av.z; As[akq + 3][arow] = av.w;
        *reinterpret_cast<float4*>(&Bs[brow][bnq]) = bv;
        __syncthreads();
        MMA16();
        __syncthreads();
    }
#pragma unroll
    for (int i = 0; i < 4; i++) {
        int tk = toks[ty + i];
        if (tk < 0) continue;
#pragma unroll
        for (int j = 0; j < 4; j++)
            dst[tk * Dm + bn + tx + j] =
                gelu_tanh(acc[i][j] + opsB[e * Dm + bn + tx + j]);
    }
}

// =========================== launch ===========================
extern "C" void kernel_launch(void* const* d_in, const int* in_sizes, int n_in,
                              void* d_out, int out_size) {
    const float* x        = (const float*)d_in[0];
    const float* W_in     = (const float*)d_in[1];
    const float* b_in     = (const float*)d_in[2];
    const float* ops_W    = (const float*)d_in[3];
    const float* ops_b    = (const float*)d_in[4];
    const float* sym_W    = (const float*)d_in[5];
    const float* router_W = (const float*)d_in[6];
    const float* router_b = (const float*)d_in[7];
    (void)in_sizes; (void)n_in; (void)out_size;

    float* out   = (float*)d_out;                 // [B, D]
    float* progf = out + Bsz * Dm;                // [B, HOPS] as float
    float* sym   = progf + Bsz * HOPS;            // [B, N, S]

    const int copyBlocks = (Bsz * Dm / 4) / 256;  // 2048

    gemm_z_kernel  <<<dim3(Bsz / 64, Dm / 64), 256>>>(x, W_in, b_in);
    gemm_sym_kernel<<<dim3(Bsz / 64, (Nn * Ss) / 64), 256>>>(sym_W, sym);
    mean_kernel    <<<(Bsz * Ss) / 256, 256>>>(sym);
    router_kernel  <<<Bsz / 8, 288>>>(router_W, router_b, progf);
    schedule_kernel<<<1, 512>>>();

    // hop 0: z -> buf
    copy_kernel<<<copyBlocks, 256>>>(0, 1, out);
    hop_kernel <<<dim3(MAXT, Dm / 64), 256>>>(0, 0, 1, out, ops_W, ops_b);
    // hop 1: buf -> z
    copy_kernel<<<copyBlocks, 256>>>(1, 0, out);
    hop_kernel <<<dim3(MAXT, Dm / 64), 256>>>(1, 1, 0, out, ops_W, ops_b);
    // hop 2: z -> buf
    copy_kernel<<<copyBlocks, 256>>>(0, 1, out);
    hop_kernel <<<dim3(MAXT, Dm / 64), 256>>>(2, 0, 1, out, ops_W, ops_b);
    // hop 3: buf -> d_out (final)
    copy_kernel<<<copyBlocks, 256>>>(1, 2, out);
    hop_kernel <<<dim3(MAXT, Dm / 64), 256>>>(3, 1, 2, out, ops_W, ops_b);
}

// round 4
// speedup vs baseline: 2.4826x; 1.3398x over previous
#include <cuda_runtime.h>
#include <math.h>
#include <stdint.h>

// Problem constants (fixed by the reference)
#define Bsz   4096
#define INDIM 1024
#define Dm    512
#define Nn    8
#define Ss    128
#define HOPS  4
#define MAXT  72      // max token tiles per hop: 4096/64 + 8

// -------- device scratch (no allocations allowed) --------
__device__ float g_z[Bsz * Dm];        // z / ping buffer
__device__ float g_buf[Bsz * Dm];      // pong buffer
__device__ float g_symmean[Bsz * Ss];
__device__ int   g_prog[Bsz * HOPS];
__device__ int   g_order[HOPS][Bsz];
__device__ int   g_tileE[HOPS][MAXT];
__device__ int   g_tileS[HOPS][MAXT];
__device__ int   g_tileC[HOPS][MAXT];
__device__ int   g_numTiles[HOPS];

__device__ __forceinline__ float gelu_tanh(float x) {
    float x3 = x * x * x;
    return 0.5f * x * (1.0f + tanhf(0.7978845608028654f * (x + 0.044715f * x3)));
}

// ---------------- 3xTF32 helpers ----------------
__device__ __forceinline__ uint32_t f2tf(float v) {
    uint32_t r; asm("cvt.rna.tf32.f32 %0, %1;" : "=r"(r) : "f"(v)); return r;
}
__device__ __forceinline__ void split4(float4 v, uint4& h, uint4& l) {
    h.x = f2tf(v.x); h.y = f2tf(v.y); h.z = f2tf(v.z); h.w = f2tf(v.w);
    l.x = f2tf(__fsub_rn(v.x, __uint_as_float(h.x)));
    l.y = f2tf(__fsub_rn(v.y, __uint_as_float(h.y)));
    l.z = f2tf(__fsub_rn(v.z, __uint_as_float(h.z)));
    l.w = f2tf(__fsub_rn(v.w, __uint_as_float(h.w)));
}

#define MMA(d, a, b)                                                          \
    asm("mma.sync.aligned.m16n8k8.row.col.f32.tf32.tf32.f32 "                 \
        "{%0,%1,%2,%3}, {%4,%5,%6,%7}, {%8,%9}, {%0,%1,%2,%3};"               \
        : "+f"(d[0]), "+f"(d[1]), "+f"(d[2]), "+f"(d[3])                      \
        : "r"(a[0]), "r"(a[1]), "r"(a[2]), "r"(a[3]), "r"(b[0]), "r"(b[1]))

// One k8 step: warp (wm,wn) computes its 32x32 with 3xTF32 (2 m-tiles x 4 n-tiles).
__device__ __forceinline__ void mma_k8(
    const uint32_t Ah[64][36], const uint32_t Al[64][36],
    const uint32_t Bh[32][68], const uint32_t Bl[32][68],
    int wm, int wn, int lane, int k8, float acc[2][4][4]) {
    const int lr = lane >> 2, lc = lane & 3;
    uint32_t ah[2][4], al[2][4];
#pragma unroll
    for (int mt = 0; mt < 2; mt++) {
        int m = wm * 32 + mt * 16 + lr;
        ah[mt][0] = Ah[m][k8 + lc];       ah[mt][1] = Ah[m + 8][k8 + lc];
        ah[mt][2] = Ah[m][k8 + lc + 4];   ah[mt][3] = Ah[m + 8][k8 + lc + 4];
        al[mt][0] = Al[m][k8 + lc];       al[mt][1] = Al[m + 8][k8 + lc];
        al[mt][2] = Al[m][k8 + lc + 4];   al[mt][3] = Al[m + 8][k8 + lc + 4];
    }
#pragma unroll
    for (int nt = 0; nt < 4; nt++) {
        int n = wn * 32 + nt * 8 + lr;
        uint32_t bh[2], bl[2];
        bh[0] = Bh[k8 + lc][n]; bh[1] = Bh[k8 + lc + 4][n];
        bl[0] = Bl[k8 + lc][n]; bl[1] = Bl[k8 + lc + 4][n];
#pragma unroll
        for (int mt = 0; mt < 2; mt++) {
            MMA(acc[mt][nt], ah[mt], bl);
            MMA(acc[mt][nt], al[mt], bh);
            MMA(acc[mt][nt], ah[mt], bh);
        }
    }
}

// ============ GEMM 1 (3xTF32): z = x @ W_in + b_in  [4096,1024]x[1024,512] ============
__global__ __launch_bounds__(128) void gemm_z_tc(
    const float* __restrict__ A, const float* __restrict__ W, const float* __restrict__ bias) {
    __shared__ uint32_t Ah[64][36], Al[64][36], Bh[32][68], Bl[32][68];
    const int tid = threadIdx.x, lane = tid & 31, warp = tid >> 5;
    const int wm = warp & 1, wn = warp >> 1;
    const int bm = blockIdx.x * 64, bn = blockIdx.y * 64;
    const int mrow = tid >> 3, kq = (tid & 7) * 4;
    const int brow = tid >> 4, nq = (tid & 15) * 4;
    float acc[2][4][4] = {};
    for (int k0 = 0; k0 < INDIM; k0 += 32) {
#pragma unroll
        for (int i = 0; i < 4; i++) {
            int m = i * 16 + mrow;
            float4 v = *reinterpret_cast<const float4*>(A + (size_t)(bm + m) * INDIM + k0 + kq);
            uint4 h, l; split4(v, h, l);
            *reinterpret_cast<uint4*>(&Ah[m][kq]) = h;
            *reinterpret_cast<uint4*>(&Al[m][kq]) = l;
            int kk = i * 8 + brow;
            float4 w = *reinterpret_cast<const float4*>(W + (size_t)(k0 + kk) * Dm + bn + nq);
            split4(w, h, l);
            *reinterpret_cast<uint4*>(&Bh[kk][nq]) = h;
            *reinterpret_cast<uint4*>(&Bl[kk][nq]) = l;
        }
        __syncthreads();
        mma_k8(Ah, Al, Bh, Bl, wm, wn, lane, 0, acc);
        mma_k8(Ah, Al, Bh, Bl, wm, wn, lane, 8, acc);
        mma_k8(Ah, Al, Bh, Bl, wm, wn, lane, 16, acc);
        mma_k8(Ah, Al, Bh, Bl, wm, wn, lane, 24, acc);
        __syncthreads();
    }
    const int lr = lane >> 2, lc = lane & 3;
#pragma unroll
    for (int mt = 0; mt < 2; mt++)
#pragma unroll
        for (int nt = 0; nt < 4; nt++) {
            int m0 = bm + wm * 32 + mt * 16 + lr;
            int n0 = bn + wn * 32 + nt * 8 + 2 * lc;
            float b0 = bias[n0], b1 = bias[n0 + 1];
            g_z[(size_t)m0 * Dm + n0]           = acc[mt][nt][0] + b0;
            g_z[(size_t)m0 * Dm + n0 + 1]       = acc[mt][nt][1] + b1;
            g_z[(size_t)(m0 + 8) * Dm + n0]     = acc[mt][nt][2] + b0;
            g_z[(size_t)(m0 + 8) * Dm + n0 + 1] = acc[mt][nt][3] + b1;
        }
}

// ======= GEMM 2 (3xTF32): sym[b, n*128+s] = sum_d z[b,d]*sym_W[n,d,s]  (K=512) =======
__global__ __launch_bounds__(128) void gemm_sym_tc(
    const float* __restrict__ symW, float* __restrict__ symOut) {
    __shared__ uint32_t Ah[64][36], Al[64][36], Bh[32][68], Bl[32][68];
    const int tid = threadIdx.x, lane = tid & 31, warp = tid >> 5;
    const int wm = warp & 1, wn = warp >> 1;
    const int bm = blockIdx.x * 64, bn = blockIdx.y * 64;
    const int mrow = tid >> 3, kq = (tid & 7) * 4;
    const int brow = tid >> 4, nq = (tid & 15) * 4;
    const float* bptr = symW + (size_t)(bn >> 7) * (Dm * Ss) + (bn & 127);
    float acc[2][4][4] = {};
    for (int k0 = 0; k0 < Dm; k0 += 32) {
#pragma unroll
        for (int i = 0; i < 4; i++) {
            int m = i * 16 + mrow;
            float4 v = *reinterpret_cast<const float4*>(g_z + (size_t)(bm + m) * Dm + k0 + kq);
            uint4 h, l; split4(v, h, l);
            *reinterpret_cast<uint4*>(&Ah[m][kq]) = h;
            *reinterpret_cast<uint4*>(&Al[m][kq]) = l;
            int kk = i * 8 + brow;
            float4 w = *reinterpret_cast<const float4*>(bptr + (size_t)(k0 + kk) * Ss + nq);
            split4(w, h, l);
            *reinterpret_cast<uint4*>(&Bh[kk][nq]) = h;
            *reinterpret_cast<uint4*>(&Bl[kk][nq]) = l;
        }
        __syncthreads();
        mma_k8(Ah, Al, Bh, Bl, wm, wn, lane, 0, acc);
        mma_k8(Ah, Al, Bh, Bl, wm, wn, lane, 8, acc);
        mma_k8(Ah, Al, Bh, Bl, wm, wn, lane, 16, acc);
        mma_k8(Ah, Al, Bh, Bl, wm, wn, lane, 24, acc);
        __syncthreads();
    }
    const int lr = lane >> 2, lc = lane & 3;
#pragma unroll
    for (int mt = 0; mt < 2; mt++)
#pragma unroll
        for (int nt = 0; nt < 4; nt++) {
            int m0 = bm + wm * 32 + mt * 16 + lr;
            int n0 = bn + wn * 32 + nt * 8 + 2 * lc;
            symOut[(size_t)m0 * (Nn * Ss) + n0]           = acc[mt][nt][0];
            symOut[(size_t)m0 * (Nn * Ss) + n0 + 1]       = acc[mt][nt][1];
            symOut[(size_t)(m0 + 8) * (Nn * Ss) + n0]     = acc[mt][nt][2];
            symOut[(size_t)(m0 + 8) * (Nn * Ss) + n0 + 1] = acc[mt][nt][3];
        }
}

// ================== symmean[b,s] = mean_n sym[b,n,s] ==================
__global__ void mean_kernel(const float* __restrict__ symOut) {
    int i = blockIdx.x * blockDim.x + threadIdx.x;
    int b = i >> 7, s = i & 127;
    const float* p = symOut + (size_t)b * (Nn * Ss) + s;
    float sum = 0.f;
#pragma unroll
    for (int n = 0; n < Nn; n++) sum += p[n * Ss];
    g_symmean[i] = sum * 0.125f;
}

// ====== router: compensated-fp32 logits + argmax -> prog (known-good from R3) ======
__global__ __launch_bounds__(288) void router_kernel(
    const float* __restrict__ RW, const float* __restrict__ rb, float* __restrict__ progf) {
    __shared__ float rin[8][644];
    __shared__ float lg[8][36];
    const int b0 = blockIdx.x * 8;
    const int tid = threadIdx.x;
    for (int i = tid; i < 8 * 640; i += 288) {
        int t = i / 640, k = i - t * 640;
        rin[t][k] = (k < Dm) ? g_z[(size_t)(b0 + t) * Dm + k]
                             : g_symmean[(size_t)(b0 + t) * Ss + (k - Dm)];
    }
    __syncthreads();
    {
        const int t = tid / 36, j = tid - t * 36;
        const float* rw = RW + j;
        float s[4] = {0.f, 0.f, 0.f, 0.f};
        float c[4] = {0.f, 0.f, 0.f, 0.f};
#pragma unroll 2
        for (int k = 0; k < 640; k += 4) {
#pragma unroll
            for (int i = 0; i < 4; i++) {
                float x = rin[t][k + i];
                float w = __ldg(&rw[(k + i) * 36]);
                float p = __fmul_rn(x, w);
                float e = __fmaf_rn(x, w, -p);
                float t1  = __fadd_rn(s[i], p);
                float bb  = __fsub_rn(t1, s[i]);
                float er1 = __fadd_rn(__fsub_rn(s[i], __fsub_rn(t1, bb)),
                                      __fsub_rn(p, bb));
                s[i] = t1;
                c[i] = __fadd_rn(c[i], __fadd_rn(er1, e));
            }
        }
        float S = rb[j], C = 0.f;
#pragma unroll
        for (int i = 0; i < 4; i++) {
            float t1  = __fadd_rn(S, s[i]);
            float bb  = __fsub_rn(t1, S);
            float er1 = __fadd_rn(__fsub_rn(S, __fsub_rn(t1, bb)),
                                  __fsub_rn(s[i], bb));
            S = t1;
            C = __fadd_rn(C, __fadd_rn(er1, c[i]));
        }
        lg[t][j] = __fadd_rn(S, C);
    }
    __syncthreads();
    if (tid < 32) {
        int t = tid >> 2, h = tid & 3;
        const float* l = &lg[t][h * 9];
        float best = l[0]; int bi = 0;
#pragma unroll
        for (int j = 1; j < 9; j++)
            if (l[j] > best) { best = l[j]; bi = j; }
        g_prog[(b0 + t) * HOPS + h] = bi;
        progf[(b0 + t) * HOPS + h] = (float)bi;
    }
}

// ======= schedule: group active tokens by (hop, expert); build 64-row tiles =======
__global__ void schedule_kernel() {
    __shared__ int cnt[HOPS][Nn];
    __shared__ int cur[HOPS][Nn];
    const int tid = threadIdx.x;
    if (tid < HOPS * Nn) cnt[tid / Nn][tid % Nn] = 0;
    __syncthreads();
    for (int b = tid; b < Bsz; b += blockDim.x) {
        bool act = true;
        for (int t = 0; t < HOPS; t++) {
            int e = g_prog[b * HOPS + t];
            act = act && (e != Nn);
            if (act) atomicAdd(&cnt[t][e], 1);
        }
    }
    __syncthreads();
    if (tid < HOPS) {
        int t = tid, p = 0, nt = 0;
        for (int e = 0; e < Nn; e++) {
            cur[t][e] = p;
            int c = cnt[t][e], q = p;
            while (c > 0) {
                g_tileE[t][nt] = e; g_tileS[t][nt] = q;
                g_tileC[t][nt] = (c < 64) ? c : 64;
                q += 64; c -= 64; nt++;
            }
            p += cnt[t][e];
        }
        g_numTiles[t] = nt;
    }
    __syncthreads();
    for (int b = tid; b < Bsz; b += blockDim.x) {
        bool act = true;
        for (int t = 0; t < HOPS; t++) {
            int e = g_prog[b * HOPS + t];
            act = act && (e != Nn);
            if (act) { int p = atomicAdd(&cur[t][e], 1); g_order[t][p] = b; }
        }
    }
}

// ===== copy cur -> next (inactive tokens keep value; hop GEMM overwrites actives) =====
__global__ void copy_kernel(int srcSel, int dstSel, float* __restrict__ outbase) {
    const float* s = (srcSel == 0) ? g_z : g_buf;
    float* d = (dstSel == 0) ? g_z : (dstSel == 1) ? g_buf : outbase;
    int i = blockIdx.x * blockDim.x + threadIdx.x;
    reinterpret_cast<float4*>(d)[i] = reinterpret_cast<const float4*>(s)[i];
}

// == hop (3xTF32): dst[tok] = gelu(src[tok] @ ops_W[e] + ops_b[e]), gather/scatter ==
__global__ __launch_bounds__(128) void hop_tc(
    int hop, int srcSel, int dstSel, float* __restrict__ outbase,
    const float* __restrict__ opsW, const float* __restrict__ opsB) {
    if ((int)blockIdx.x >= g_numTiles[hop]) return;
    const float* src = (srcSel == 0) ? g_z : g_buf;
    float* dst = (dstSel == 0) ? g_z : (dstSel == 1) ? g_buf : outbase;
    const int e     = g_tileE[hop][blockIdx.x];
    const int start = g_tileS[hop][blockIdx.x];
    const int cnt   = g_tileC[hop][blockIdx.x];
    const int bn    = blockIdx.y * 64;
    __shared__ int toks[64];
    __shared__ uint32_t Ah[64][36], Al[64][36], Bh[32][68], Bl[32][68];
    const int tid = threadIdx.x, lane = tid & 31, warp = tid >> 5;
    const int wm = warp & 1, wn = warp >> 1;
    const int mrow = tid >> 3, kq = (tid & 7) * 4;
    const int brow = tid >> 4, nq = (tid & 15) * 4;
    if (tid < 64) toks[tid] = (tid < cnt) ? g_order[hop][start + tid] : -1;
    __syncthreads();
    int myTok[4];
#pragma unroll
    for (int i = 0; i < 4; i++) myTok[i] = toks[i * 16 + mrow];
    const float* W = opsW + (size_t)e * (Dm * Dm);
    float acc[2][4][4] = {};
    for (int k0 = 0; k0 < Dm; k0 += 32) {
#pragma unroll
        for (int i = 0; i < 4; i++) {
            int m = i * 16 + mrow;
            float4 v = make_float4(0.f, 0.f, 0.f, 0.f);
            if (myTok[i] >= 0)
                v = *reinterpret_cast<const float4*>(src + (size_t)myTok[i] * Dm + k0 + kq);
            uint4 h, l; split4(v, h, l);
            *reinterpret_cast<uint4*>(&Ah[m][kq]) = h;
            *reinterpret_cast<uint4*>(&Al[m][kq]) = l;
            int kk = i * 8 + brow;
            float4 w = *reinterpret_cast<const float4*>(W + (size_t)(k0 + kk) * Dm + bn + nq);
            split4(w, h, l);
            *reinterpret_cast<uint4*>(&Bh[kk][nq]) = h;
            *reinterpret_cast<uint4*>(&Bl[kk][nq]) = l;
        }
        __syncthreads();
        mma_k8(Ah, Al, Bh, Bl, wm, wn, lane, 0, acc);
        mma_k8(Ah, Al, Bh, Bl, wm, wn, lane, 8, acc);
        mma_k8(Ah, Al, Bh, Bl, wm, wn, lane, 16, acc);
        mma_k8(Ah, Al, Bh, Bl, wm, wn, lane, 24, acc);
        __syncthreads();
    }
    const int lr = lane >> 2, lc = lane & 3;
#pragma unroll
    for (int mt = 0; mt < 2; mt++) {
        int r0 = wm * 32 + mt * 16 + lr;
        int tk0 = toks[r0], tk1 = toks[r0 + 8];
#pragma unroll
        for (int nt = 0; nt < 4; nt++) {
            int n0 = bn + wn * 32 + nt * 8 + 2 * lc;
            float b0 = opsB[e * Dm + n0], b1 = opsB[e * Dm + n0 + 1];
            if (tk0 >= 0) {
                dst[(size_t)tk0 * Dm + n0]     = gelu_tanh(acc[mt][nt][0] + b0);
                dst[(size_t)tk0 * Dm + n0 + 1] = gelu_tanh(acc[mt][nt][1] + b1);
            }
            if (tk1 >= 0) {
                dst[(size_t)tk1 * Dm + n0]     = gelu_tanh(acc[mt][nt][2] + b0);
                dst[(size_t)tk1 * Dm + n0 + 1] = gelu_tanh(acc[mt][nt][3] + b1);
            }
        }
    }
}

// =========================== launch ===========================
extern "C" void kernel_launch(void* const* d_in, const int* in_sizes, int n_in,
                              void* d_out, int out_size) {
    const float* x        = (const float*)d_in[0];
    const float* W_in     = (const float*)d_in[1];
    const float* b_in     = (const float*)d_in[2];
    const float* ops_W    = (const float*)d_in[3];
    const float* ops_b    = (const float*)d_in[4];
    const float* sym_W    = (const float*)d_in[5];
    const float* router_W = (const float*)d_in[6];
    const float* router_b = (const float*)d_in[7];
    (void)in_sizes; (void)n_in; (void)out_size;

    float* out   = (float*)d_out;                 // [B, D]
    float* progf = out + Bsz * Dm;                // [B, HOPS] as float
    float* sym   = progf + Bsz * HOPS;            // [B, N, S]

    const int copyBlocks = (Bsz * Dm / 4) / 256;  // 2048

    gemm_z_tc   <<<dim3(Bsz / 64, Dm / 64), 128>>>(x, W_in, b_in);
    gemm_sym_tc <<<dim3(Bsz / 64, (Nn * Ss) / 64), 128>>>(sym_W, sym);
    mean_kernel <<<(Bsz * Ss) / 256, 256>>>(sym);
    router_kernel<<<Bsz / 8, 288>>>(router_W, router_b, progf);
    schedule_kernel<<<1, 512>>>();

    // hop 0: z -> buf
    copy_kernel<<<copyBlocks, 256>>>(0, 1, out);
    hop_tc     <<<dim3(MAXT, Dm / 64), 128>>>(0, 0, 1, out, ops_W, ops_b);
    // hop 1: buf -> z
    copy_kernel<<<copyBlocks, 256>>>(1, 0, out);
    hop_tc     <<<dim3(MAXT, Dm / 64), 128>>>(1, 1, 0, out, ops_W, ops_b);
    // hop 2: z -> buf
    copy_kernel<<<copyBlocks, 256>>>(0, 1, out);
    hop_tc     <<<dim3(MAXT, Dm / 64), 128>>>(2, 0, 1, out, ops_W, ops_b);
    // hop 3: buf -> d_out (final)
    copy_kernel<<<copyBlocks, 256>>>(1, 2, out);
    hop_tc     <<<dim3(MAXT, Dm / 64), 128>>>(3, 1, 2, out, ops_W, ops_b);
}